// round 3
// baseline (speedup 1.0000x reference)
#include <cuda_runtime.h>
#include <cstdint>

#define NN 100000
#define NE 3200000
#define FIN 512
#define H   16
#define FOUT 128
#define NC  3

// ---------------- scratch (no allocations allowed) ----------------
__device__ float4 g_P1[NN * 4];    // layer-1 projected (pre-agg), 16 f/node, row = 64B
__device__ float4 g_P2[NN * 4];    // relu(...)*norm_src for layer 2
__device__ int    g_deg_out[NN];
__device__ int    g_deg_in[NN];
__device__ int    g_off[NN];       // exclusive prefix sum of deg_in
__device__ int    g_cursor[NN];    // bucket write cursors
__device__ int    g_csr_src[NE];   // src ids grouped by dst
__device__ float  g_Wc[H * NC];    // W2 @ Wfc  (16x3)
__device__ float  g_bc[NC];        // b2 @ Wfc + bfc
__device__ int    g_is64;

// ---------------- f32x2 packed math helpers ----------------
typedef unsigned long long u64;

__device__ __forceinline__ u64 pack2(float a, float b) {
    u64 r; asm("mov.b64 %0, {%1, %2};" : "=l"(r) : "f"(a), "f"(b)); return r;
}
__device__ __forceinline__ void unpack2(u64 v, float& a, float& b) {
    asm("mov.b64 {%0, %1}, %2;" : "=f"(a), "=f"(b) : "l"(v));
}
__device__ __forceinline__ u64 fma2(u64 a, u64 b, u64 c) {
    u64 d; asm("fma.rn.f32x2 %0, %1, %2, %3;" : "=l"(d) : "l"(a), "l"(b), "l"(c)); return d;
}
__device__ __forceinline__ u64 add2(u64 a, u64 b) {
    u64 d; asm("add.rn.f32x2 %0, %1, %2;" : "=l"(d) : "l"(a), "l"(b)); return d;
}
__device__ __forceinline__ u64 mul2(u64 a, u64 b) {
    u64 d; asm("mul.rn.f32x2 %0, %1, %2;" : "=l"(d) : "l"(a), "l"(b)); return d;
}

__device__ __forceinline__ int eidx(const void* p, int e, int is64) {
    if (is64) return (int)__ldcs(((const long long*)p) + e);
    return __ldcs(((const int*)p) + e);
}

// ---------------- index dtype detection ----------------
__global__ void k_detect(const unsigned* __restrict__ w) {
    if (threadIdx.x == 0) {
        int is64 = 1;
        #pragma unroll 1
        for (int i = 0; i < 256; i++) {
            if (w[2 * i + 1] != 0u) { is64 = 0; break; }
        }
        g_is64 = is64;
    }
}

// ---------------- fused W2@Wfc ----------------
__global__ void k_wc(const float* __restrict__ W2, const float* __restrict__ b2,
                     const float* __restrict__ Wfc, const float* __restrict__ bfc) {
    int t = threadIdx.x;
    if (t < H * NC) {
        int k = t / NC, c = t % NC;
        float s = 0.f;
        #pragma unroll 4
        for (int j = 0; j < FOUT; j++) s += W2[k * FOUT + j] * Wfc[j * NC + c];
        g_Wc[t] = s;
    }
    if (t < NC) {
        float s = bfc[t];
        #pragma unroll 4
        for (int j = 0; j < FOUT; j++) s += b2[j] * Wfc[j * NC + t];
        g_bc[t] = s;
    }
}

// ---------------- degrees ----------------
__global__ void k_zero_deg() {
    int i = blockIdx.x * blockDim.x + threadIdx.x;
    if (i < NN) { g_deg_out[i] = 0; g_deg_in[i] = 0; }
}

__global__ void k_degree(const void* __restrict__ src, const void* __restrict__ dst) {
    int e = blockIdx.x * blockDim.x + threadIdx.x;
    if (e >= NE) return;
    int is64 = g_is64;
    atomicAdd(&g_deg_out[eidx(src, e, is64)], 1);
    atomicAdd(&g_deg_in[eidx(dst, e, is64)], 1);
}

// ---------------- exclusive scan of deg_in (single block) ----------------
__global__ void __launch_bounds__(1024) k_scan() {
    __shared__ int part[1024];
    const int CH = (NN + 1023) / 1024;  // 98
    int t = threadIdx.x;
    int base = t * CH;
    int s = 0;
    for (int i = 0; i < CH; i++) {
        int idx = base + i;
        if (idx < NN) s += g_deg_in[idx];
    }
    part[t] = s;
    __syncthreads();
    for (int off = 1; off < 1024; off <<= 1) {
        int v = (t >= off) ? part[t - off] : 0;
        __syncthreads();
        part[t] += v;
        __syncthreads();
    }
    int ex = (t > 0) ? part[t - 1] : 0;
    for (int i = 0; i < CH; i++) {
        int idx = base + i;
        if (idx < NN) {
            g_off[idx] = ex;
            g_cursor[idx] = ex;
            ex += g_deg_in[idx];
        }
    }
}

// ---------------- bucket edges by dst ----------------
__global__ void k_bucket(const void* __restrict__ src, const void* __restrict__ dst) {
    int e = blockIdx.x * blockDim.x + threadIdx.x;
    if (e >= NE) return;
    int is64 = g_is64;
    int s = eidx(src, e, is64);
    int d = eidx(dst, e, is64);
    int p = atomicAdd(&g_cursor[d], 1);
    g_csr_src[p] = s;
}

// ---------------- layer-1 GEMM: P1 = norm_src * (feat @ W1) ----------------
// Warp handles 4 rows; W1 pairs packed as f32x2. Wp[kk][i] (kk = k-pair idx).
__global__ void __launch_bounds__(256) k_gemm1(const float* __restrict__ feat,
                                               const float* __restrict__ W1) {
    __shared__ float2 Wp[8 * FIN];  // [kk][i]
    for (int t = threadIdx.x; t < FIN * 8; t += 256) {
        int i = t >> 3, kk = t & 7;
        Wp[kk * FIN + i] = ((const float2*)W1)[t];  // (W1[i][2kk], W1[i][2kk+1])
    }
    __syncthreads();
    const u64* WpU = (const u64*)Wp;

    int warp = threadIdx.x >> 5, lane = threadIdx.x & 31;
    int row0 = (blockIdx.x * 8 + warp) * 4;
    if (row0 >= NN) return;

    u64 acc[4][8];
    #pragma unroll
    for (int r = 0; r < 4; r++)
        #pragma unroll
        for (int kk = 0; kk < 8; kk++) acc[r][kk] = 0ull;

    #pragma unroll
    for (int m = 0; m < 16; m++) {
        int i = lane + 32 * m;
        u64 wk[8];
        #pragma unroll
        for (int kk = 0; kk < 8; kk++) wk[kk] = WpU[kk * FIN + i];
        #pragma unroll
        for (int r = 0; r < 4; r++) {
            int row = row0 + r;
            float xv = (row < NN) ? __ldcs(feat + (size_t)row * FIN + i) : 0.f;
            u64 xx = pack2(xv, xv);
            #pragma unroll
            for (int kk = 0; kk < 8; kk++) acc[r][kk] = fma2(xx, wk[kk], acc[r][kk]);
        }
    }

    // warp reduce (packed)
    #pragma unroll
    for (int r = 0; r < 4; r++)
        #pragma unroll
        for (int kk = 0; kk < 8; kk++)
            #pragma unroll
            for (int off = 16; off > 0; off >>= 1)
                acc[r][kk] = add2(acc[r][kk], __shfl_xor_sync(0xffffffffu, acc[r][kk], off));

    if (lane == 0) {
        #pragma unroll
        for (int r = 0; r < 4; r++) {
            int row = row0 + r;
            if (row >= NN) break;
            float ns = rsqrtf(fmaxf((float)g_deg_out[row], 1.f));
            u64 nsp = pack2(ns, ns);
            #pragma unroll
            for (int c = 0; c < 4; c++) {
                float a, b, cc, d;
                unpack2(mul2(acc[r][2 * c + 0], nsp), a, b);
                unpack2(mul2(acc[r][2 * c + 1], nsp), cc, d);
                g_P1[row * 4 + c] = make_float4(a, b, cc, d);
            }
        }
    }
}

// ---------------- gather passes: warp per node, 4 lanes per edge -------------
// lane = 4*e_slot + q : loads 16B quarter q of P[s]; 8 edges per warp-iter.
// PASS 1: acc -> P2 = relu(acc*nd + b1)*ns
// PASS 2: acc -> out = nd*(acc @ Wc) + bc
template <int PASS>
__global__ void __launch_bounds__(256) k_gather(const float* __restrict__ b1,
                                                float* __restrict__ out) {
    int warp = threadIdx.x >> 5, lane = threadIdx.x & 31;
    int n = blockIdx.x * 8 + warp;
    if (n >= NN) return;

    int base = g_off[n];
    int deg = g_deg_in[n];
    int e_slot = lane >> 2;
    int q = lane & 3;

    const ulonglong2* P = (PASS == 1) ? (const ulonglong2*)g_P1 : (const ulonglong2*)g_P2;

    u64 acc0 = 0ull, acc1 = 0ull;
    for (int it = 0; it * 8 < deg; it++) {
        int eo = it * 8 + e_slot;
        if (eo < deg) {
            int s = __ldg(g_csr_src + base + eo);
            ulonglong2 v = __ldg(P + (size_t)s * 4 + q);
            acc0 = add2(acc0, v.x);
            acc1 = add2(acc1, v.y);
        }
    }
    // reduce across the 8 edge slots (lanes differing in bits 2..4)
    #pragma unroll
    for (int off = 4; off < 32; off <<= 1) {
        acc0 = add2(acc0, __shfl_xor_sync(0xffffffffu, acc0, off));
        acc1 = add2(acc1, __shfl_xor_sync(0xffffffffu, acc1, off));
    }

    float nd = rsqrtf(fmaxf((float)deg, 1.f));
    float a0, a1, a2, a3;
    unpack2(acc0, a0, a1);
    unpack2(acc1, a2, a3);

    if (PASS == 1) {
        float ns = rsqrtf(fmaxf((float)g_deg_out[n], 1.f));
        float4 bb = ((const float4*)b1)[q];
        float4 o;
        o.x = fmaxf(fmaf(a0, nd, bb.x), 0.f) * ns;
        o.y = fmaxf(fmaf(a1, nd, bb.y), 0.f) * ns;
        o.z = fmaxf(fmaf(a2, nd, bb.z), 0.f) * ns;
        o.w = fmaxf(fmaf(a3, nd, bb.w), 0.f) * ns;
        if (lane < 4) g_P2[n * 4 + q] = o;
    } else {
        // partial dot with Wc rows 4q..4q+3
        float z0 = a0 * nd, z1 = a1 * nd, z2 = a2 * nd, z3 = a3 * nd;
        float o[NC];
        #pragma unroll
        for (int c = 0; c < NC; c++) {
            o[c] = z0 * g_Wc[(4 * q + 0) * NC + c] + z1 * g_Wc[(4 * q + 1) * NC + c]
                 + z2 * g_Wc[(4 * q + 2) * NC + c] + z3 * g_Wc[(4 * q + 3) * NC + c];
        }
        #pragma unroll
        for (int c = 0; c < NC; c++) {
            o[c] += __shfl_xor_sync(0xffffffffu, o[c], 1);
            o[c] += __shfl_xor_sync(0xffffffffu, o[c], 2);
        }
        if (lane == 0) {
            out[n * 3 + 0] = o[0] + g_bc[0];
            out[n * 3 + 1] = o[1] + g_bc[1];
            out[n * 3 + 2] = o[2] + g_bc[2];
        }
    }
}

// ---------------- launch ----------------
extern "C" void kernel_launch(void* const* d_in, const int* in_sizes, int n_in,
                              void* d_out, int out_size) {
    const float* features = (const float*)d_in[0];
    const void*  src      = d_in[1];
    const void*  dst      = d_in[2];
    const float* W1       = (const float*)d_in[3];
    const float* b1       = (const float*)d_in[4];
    const float* W2       = (const float*)d_in[5];
    const float* b2       = (const float*)d_in[6];
    const float* Wfc      = (const float*)d_in[7];
    const float* bfc      = (const float*)d_in[8];
    float* out = (float*)d_out;

    (void)in_sizes; (void)n_in; (void)out_size;

    const int EB = (NE + 255) / 256;
    const int NB = (NN + 255) / 256;
    const int GB = (NN + 7) / 8;  // gather: 8 warps/block, warp per node

    k_wc<<<1, 64>>>(W2, b2, Wfc, bfc);
    k_detect<<<1, 32>>>((const unsigned*)src);
    k_zero_deg<<<NB, 256>>>();
    k_degree<<<EB, 256>>>(src, dst);
    k_scan<<<1, 1024>>>();
    k_bucket<<<EB, 256>>>(src, dst);
    k_gemm1<<<(NN + 31) / 32, 256>>>(features, W1);
    k_gather<1><<<GB, 256>>>(b1, out);
    k_gather<2><<<GB, 256>>>(b1, out);
}